// round 5
// baseline (speedup 1.0000x reference)
#include <cuda_runtime.h>
#include <cuda_bf16.h>
#include <cstdint>
#include <math.h>

// ---------------- device scratch (allocation-free) ----------------
__device__ __align__(16) __nv_bfloat16 g_xhi[256 * 1024];
__device__ __align__(16) __nv_bfloat16 g_xlo[256 * 1024];
__device__ __align__(16) __nv_bfloat16 g_Whi[512 * 1024];
__device__ __align__(16) __nv_bfloat16 g_Wlo[512 * 1024];
__device__ __align__(16) __nv_bfloat16 g_uT [1024 * 512];   // uT[n][k] = bf16(expm1(u[k][n]))
__device__ __align__(16) __nv_bfloat16 g_Ebf[256 * 512];    // bf16(E)
__device__ float g_rs[16 * 256];                            // per-(ntile,row) fp32 rowsums of E

// ---------------- helpers ----------------
__device__ __forceinline__ uint32_t smem_u32(const void* p) {
    uint32_t a;
    asm("{ .reg .u64 t; cvta.to.shared.u64 t, %1; cvt.u32.u64 %0, t; }" : "=r"(a) : "l"(p));
    return a;
}
__device__ __forceinline__ void cp16(uint32_t dst, const void* src) {
    asm volatile("cp.async.cg.shared.global [%0], [%1], 16;" :: "r"(dst), "l"(src) : "memory");
}
#define CP_COMMIT() asm volatile("cp.async.commit_group;" ::: "memory")
#define CP_WAIT1()  asm volatile("cp.async.wait_group 1;" ::: "memory")
#define CP_WAIT0()  asm volatile("cp.async.wait_group 0;" ::: "memory")

__device__ __forceinline__ void ldsm4(uint32_t* r, uint32_t addr) {
    asm volatile("ldmatrix.sync.aligned.m8n8.x4.shared.b16 {%0,%1,%2,%3}, [%4];"
        : "=r"(r[0]), "=r"(r[1]), "=r"(r[2]), "=r"(r[3]) : "r"(addr));
}
__device__ __forceinline__ void mma_bf16(float* c, const uint32_t* a, uint32_t b0, uint32_t b1) {
    asm volatile("mma.sync.aligned.m16n8k16.row.col.f32.bf16.bf16.f32 "
        "{%0,%1,%2,%3}, {%4,%5,%6,%7}, {%8,%9}, {%0,%1,%2,%3};"
        : "+f"(c[0]), "+f"(c[1]), "+f"(c[2]), "+f"(c[3])
        : "r"(a[0]), "r"(a[1]), "r"(a[2]), "r"(a[3]), "r"(b0), "r"(b1));
}

__device__ __forceinline__ void split8(const float4& v0, const float4& v1,
                                       uint4& hi, uint4& lo) {
    float f[8] = {v0.x, v0.y, v0.z, v0.w, v1.x, v1.y, v1.z, v1.w};
    uint32_t h[4], l[4];
    #pragma unroll
    for (int i = 0; i < 4; i++) {
        __nv_bfloat16 h0 = __float2bfloat16(f[2 * i]);
        __nv_bfloat16 h1 = __float2bfloat16(f[2 * i + 1]);
        __nv_bfloat162 hp{h0, h1};
        __nv_bfloat162 lp{__float2bfloat16(f[2 * i]     - __bfloat162float(h0)),
                          __float2bfloat16(f[2 * i + 1] - __bfloat162float(h1))};
        h[i] = *(uint32_t*)&hp;
        l[i] = *(uint32_t*)&lp;
    }
    hi = make_uint4(h[0], h[1], h[2], h[3]);
    lo = make_uint4(l[0], l[1], l[2], l[3]);
}

// ============================================================
// xw_prep: bf16 hi/lo splits of x and W only (u handled inside gemm1 launch)
// blocks [0,64): x   [64,192): W.  Each thread: 4 float4 loads (MLP=4), 32B stores.
// ============================================================
__global__ __launch_bounds__(256) void xw_prep_kernel(
    const float* __restrict__ x, const float* __restrict__ W)
{
    const int b = blockIdx.x, t = threadIdx.x;
    const float4* src;
    __nv_bfloat16 *dhi, *dlo;
    int base;  // in float4 units
    if (b < 64) {
        src = (const float4*)x; dhi = g_xhi; dlo = g_xlo; base = b * 1024;
    } else {
        src = (const float4*)W; dhi = g_Whi; dlo = g_Wlo; base = (b - 64) * 1024;
    }
    float4 v0 = src[base + 0 * 256 + t];
    float4 v1 = src[base + 1 * 256 + t];
    float4 v2 = src[base + 2 * 256 + t];
    float4 v3 = src[base + 3 * 256 + t];
    uint4 hi, lo;
    split8(v0, v1, hi, lo);
    *(uint4*)&dhi[(base + 0 * 256 + t) * 4 - (t & 1) * 4] = hi;  // placeholder (fixed below)
    (void)lo;
    // NOTE: the pairing above is wrong for adjacent f4s; do it explicitly instead:
}

// The placeholder kernel above is unused; real prep below.
__global__ __launch_bounds__(256) void xw_prep2_kernel(
    const float* __restrict__ x, const float* __restrict__ W)
{
    const int b = blockIdx.x, t = threadIdx.x;
    const float4* src;
    __nv_bfloat16 *dhi, *dlo;
    int base;  // in float4 units (each block covers 1024 float4s)
    if (b < 64) {
        src = (const float4*)x; dhi = g_xhi; dlo = g_xlo; base = b * 1024;
    } else {
        src = (const float4*)W; dhi = g_Whi; dlo = g_Wlo; base = (b - 64) * 1024;
    }
    // two pairs of adjacent float4s per thread: (512 pairs per block, 256 threads)
    #pragma unroll
    for (int p = 0; p < 2; p++) {
        int idx = base + (p * 256 + t) * 2;          // first f4 of the pair
        float4 v0 = src[idx];
        float4 v1 = src[idx + 1];
        uint4 hi, lo;
        split8(v0, v1, hi, lo);
        *(uint4*)&dhi[idx * 4] = hi;
        *(uint4*)&dlo[idx * 4] = lo;
    }
}

// ============================================================
// GEMM1 + u-prep fused launch.
// blocks [0,128): GEMM1 tiles 32(M) x 32(N), K=1024 in 16 chunks of 64
// blocks [128,640): uT[n][k] = bf16(expm1(u[k][n])) 32x32 transpose tiles
// ============================================================
constexpr int G1_TILE_B  = 32 * 72 * 2;      // 4608 B (padded rows: 72 bf16)
constexpr int G1_STAGE_B = 4 * G1_TILE_B;    // Ahi|Alo|Bhi|Blo

__global__ __launch_bounds__(128) void gemm1_kernel(const float* __restrict__ u)
{
    __shared__ __align__(16) __nv_bfloat16 sm[2 * 4 * 32 * 72];
    __shared__ float srs[2][32];
    const int tid = threadIdx.x, lane = tid & 31, wid = tid >> 5;
    const int blk = blockIdx.x;

    if (blk >= 128) {
        // ---------------- u-prep path (runs concurrently with gemm tiles) ----
        __nv_bfloat16 (*tt)[33] = (__nv_bfloat16(*)[33])sm;
        const int id = blk - 128;                 // 0..511 : 32 ntiles x 16 ktiles
        const int n0 = (id & 31) * 32, k0 = (id >> 5) * 32;
        const int i = tid >> 5, j = tid & 31;     // i: 0..3
        #pragma unroll
        for (int r = 0; r < 8; r++) {
            int ki = r * 4 + i;
            tt[ki][j] = __float2bfloat16(expm1f(u[(k0 + ki) * 1024 + n0 + j]));
        }
        __syncthreads();
        #pragma unroll
        for (int r = 0; r < 8; r++) {
            int ni = r * 4 + i;
            g_uT[(n0 + ni) * 512 + k0 + j] = tt[j][ni];
        }
        return;
    }

    // ---------------- GEMM path ----------------
    const int nt = blk & 15;
    const int m0 = (blk >> 4) * 32, n0 = nt * 32;
    const uint32_t sb = smem_u32(sm);

    const __nv_bfloat16* base0 = g_xhi + m0 * 1024;
    const __nv_bfloat16* base1 = g_xlo + m0 * 1024;
    const __nv_bfloat16* base2 = g_Whi + n0 * 1024;
    const __nv_bfloat16* base3 = g_Wlo + n0 * 1024;

    const int wm = wid >> 1, wn = wid & 1;
    const int lrow = lane & 15;
    const int lk   = (lane >> 4) << 3;       // 0 or 8
    const uint32_t aRow = (uint32_t)(((wm * 16 + lrow) * 72 + lk) * 2);
    const uint32_t bRow = (uint32_t)(((wn * 16 + lrow) * 72 + lk) * 2);

    // 6 independent accumulator pairs: {hh, hl, lh} x {n-lo8, n-hi8}
    float acc_hh0[4] = {}, acc_hh1[4] = {};
    float acc_hl0[4] = {}, acc_hl1[4] = {};
    float acc_lh0[4] = {}, acc_lh1[4] = {};

    const int c8 = tid & 7;                   // 16B segment within row
    const int r8 = tid >> 3;                  // 0..15

    #define G1_ISSUE(c) do { \
        const int k0 = (c) * 64; \
        const uint32_t d0 = sb + ((c) & 1) * G1_STAGE_B; \
        _Pragma("unroll") \
        for (int ii = 0; ii < 8; ii++) { \
            const int tile = ii >> 1; \
            const int r = ((ii & 1) << 4) + r8; \
            const __nv_bfloat16* src = \
                (tile == 0 ? base0 : tile == 1 ? base1 : tile == 2 ? base2 : base3) \
                + r * 1024 + k0 + c8 * 8; \
            cp16(d0 + tile * G1_TILE_B + (uint32_t)((r * 72 + c8 * 8) * 2), src); \
        } \
        CP_COMMIT(); \
    } while (0)

    G1_ISSUE(0);
    G1_ISSUE(1);

    for (int c = 0; c < 16; c++) {
        if (c == 15) { CP_WAIT0(); } else { CP_WAIT1(); }
        __syncthreads();
        const uint32_t st = sb + (c & 1) * G1_STAGE_B;
        #pragma unroll
        for (int ks = 0; ks < 4; ks++) {
            uint32_t a_hi[4], a_lo[4], b_hi[4], b_lo[4];
            ldsm4(a_hi, st + aRow + ks * 32);
            ldsm4(a_lo, st + G1_TILE_B + aRow + ks * 32);
            ldsm4(b_hi, st + 2 * G1_TILE_B + bRow + ks * 32);
            ldsm4(b_lo, st + 3 * G1_TILE_B + bRow + ks * 32);
            mma_bf16(acc_hh0, a_hi, b_hi[0], b_hi[2]);
            mma_bf16(acc_hh1, a_hi, b_hi[1], b_hi[3]);
            mma_bf16(acc_hl0, a_hi, b_lo[0], b_lo[2]);
            mma_bf16(acc_hl1, a_hi, b_lo[1], b_lo[3]);
            mma_bf16(acc_lh0, a_lo, b_hi[0], b_hi[2]);
            mma_bf16(acc_lh1, a_lo, b_hi[1], b_hi[3]);
        }
        __syncthreads();
        if (c + 2 < 16) G1_ISSUE(c + 2);
    }
    #undef G1_ISSUE

    // combine passes
    float acc0[4], acc1[4];
    #pragma unroll
    for (int i = 0; i < 4; i++) {
        acc0[i] = acc_hh0[i] + acc_hl0[i] + acc_lh0[i];
        acc1[i] = acc_hh1[i] + acc_hl1[i] + acc_lh1[i];
    }

    // ---------- epilogue: exp, bf16 E, fp32 rowsum ----------
    const int qr = lane >> 2;              // 0..7
    const int qc = (lane & 3) * 2;
    const int mrow0 = m0 + wm * 16 + qr;
    const int mrow1 = mrow0 + 8;
    float p0 = 0.f, p1 = 0.f;
    #pragma unroll
    for (int g = 0; g < 2; g++) {
        float* acc = g ? acc1 : acc0;
        float e0 = expf(acc[0]), e1 = expf(acc[1]);
        float e2 = expf(acc[2]), e3 = expf(acc[3]);
        p0 += e0 + e1; p1 += e2 + e3;
        const int n = n0 + wn * 16 + g * 8 + qc;
        __nv_bfloat162 v0 = __floats2bfloat162_rn(e0, e1);
        __nv_bfloat162 v1 = __floats2bfloat162_rn(e2, e3);
        *(uint32_t*)&g_Ebf[mrow0 * 512 + n] = *(uint32_t*)&v0;
        *(uint32_t*)&g_Ebf[mrow1 * 512 + n] = *(uint32_t*)&v1;
    }
    p0 += __shfl_xor_sync(0xFFFFFFFFu, p0, 1);
    p0 += __shfl_xor_sync(0xFFFFFFFFu, p0, 2);
    p1 += __shfl_xor_sync(0xFFFFFFFFu, p1, 1);
    p1 += __shfl_xor_sync(0xFFFFFFFFu, p1, 2);
    if ((lane & 3) == 0) {
        srs[wn][wm * 16 + qr]     = p0;
        srs[wn][wm * 16 + qr + 8] = p1;
    }
    __syncthreads();
    if (tid < 32) g_rs[nt * 256 + m0 + tid] = srs[0][tid] + srs[1][tid];
}

// ============================================================
// GEMM2: y = E_bf16 @ uT^T + rowsum(E) + 512
// tile 32(M) x 64(N), K=512 in 8 chunks of 64; 128 thr (warp tile 16x32)
// ============================================================
constexpr int G2_A_B     = 32 * 72 * 2;           // 4608
constexpr int G2_B_B     = 64 * 72 * 2;           // 9216
constexpr int G2_STAGE_B = G2_A_B + G2_B_B;       // 13824

__global__ __launch_bounds__(128) void gemm2_kernel(float* __restrict__ Y)
{
    __shared__ __align__(16) __nv_bfloat16 sm[2 * (32 * 72 + 64 * 72)];
    __shared__ float rst[32];
    const int tid = threadIdx.x, lane = tid & 31, wid = tid >> 5;
    const int m0 = blockIdx.y * 32, n0 = blockIdx.x * 64;
    const uint32_t sb = smem_u32(sm);

    if (tid < 32) {
        float s = 512.0f;
        #pragma unroll
        for (int j = 0; j < 16; j++) s += g_rs[j * 256 + m0 + tid];
        rst[tid] = s;
    }

    const int wm = wid >> 1, wn = wid & 1;
    const int lrow = lane & 15;
    const int lk   = (lane >> 4) << 3;
    const uint32_t aRow  = (uint32_t)(((wm * 16 + lrow) * 72 + lk) * 2);
    const uint32_t b0Row = (uint32_t)(((wn * 32 + lrow) * 72 + lk) * 2);
    const uint32_t b1Row = b0Row + 16 * 72 * 2;

    float acc[4][4] = {};

    const int c8 = tid & 7;
    const int r8 = tid >> 3;

    #define G2_ISSUE(c) do { \
        const int k0 = (c) * 64; \
        const uint32_t d0 = sb + ((c) & 1) * G2_STAGE_B; \
        _Pragma("unroll") \
        for (int ii = 0; ii < 6; ii++) { \
            if (ii < 2) { \
                const int r = ii * 16 + r8; \
                cp16(d0 + (uint32_t)((r * 72 + c8 * 8) * 2), \
                     g_Ebf + (m0 + r) * 512 + k0 + c8 * 8); \
            } else { \
                const int r = (ii - 2) * 16 + r8; \
                cp16(d0 + G2_A_B + (uint32_t)((r * 72 + c8 * 8) * 2), \
                     g_uT + (n0 + r) * 512 + k0 + c8 * 8); \
            } \
        } \
        CP_COMMIT(); \
    } while (0)

    G2_ISSUE(0);
    G2_ISSUE(1);

    for (int c = 0; c < 8; c++) {
        if (c == 7) { CP_WAIT0(); } else { CP_WAIT1(); }
        __syncthreads();
        const uint32_t st = sb + (c & 1) * G2_STAGE_B;
        #pragma unroll
        for (int ks = 0; ks < 4; ks++) {
            uint32_t a[4], b0f[4], b1f[4];
            ldsm4(a,   st + aRow + ks * 32);
            ldsm4(b0f, st + G2_A_B + b0Row + ks * 32);
            ldsm4(b1f, st + G2_A_B + b1Row + ks * 32);
            mma_bf16(acc[0], a, b0f[0], b0f[2]);
            mma_bf16(acc[1], a, b0f[1], b0f[3]);
            mma_bf16(acc[2], a, b1f[0], b1f[2]);
            mma_bf16(acc[3], a, b1f[1], b1f[3]);
        }
        __syncthreads();
        if (c + 2 < 8) G2_ISSUE(c + 2);
    }
    #undef G2_ISSUE

    // ---------- epilogue ----------
    const int qr = lane >> 2;
    const int qc = (lane & 3) * 2;
    const int mrow0 = m0 + wm * 16 + qr;
    const int mrow1 = mrow0 + 8;
    const float r0v = rst[wm * 16 + qr];
    const float r1v = rst[wm * 16 + qr + 8];
    #pragma unroll
    for (int g = 0; g < 4; g++) {
        const int n = n0 + wn * 32 + g * 8 + qc;
        *(float2*)(Y + mrow0 * 1024 + n) = make_float2(acc[g][0] + r0v, acc[g][1] + r0v);
        *(float2*)(Y + mrow1 * 1024 + n) = make_float2(acc[g][2] + r1v, acc[g][3] + r1v);
    }
}

// ============================================================
extern "C" void kernel_launch(void* const* d_in, const int* in_sizes, int n_in,
                              void* d_out, int out_size)
{
    const float* x = (const float*)d_in[0];   // 256 x 1024
    const float* W = (const float*)d_in[1];   // 512 x 1024
    const float* u = (const float*)d_in[2];   // 512 x 1024
    float* y = (float*)d_out;                 // 256 x 1024

    xw_prep2_kernel<<<192, 256>>>(x, W);
    gemm1_kernel<<<640, 128>>>(u);
    gemm2_kernel<<<dim3(16, 8), 128>>>(y);
}

// round 6
// speedup vs baseline: 1.1520x; 1.1520x over previous
#include <cuda_runtime.h>
#include <cuda_bf16.h>
#include <cstdint>
#include <math.h>

// ---------------- device scratch (allocation-free) ----------------
__device__ __align__(16) __nv_bfloat16 g_Ebf[256 * 512];    // bf16(E)
__device__ float g_rs[16 * 256];                            // per-(ntile,row) fp32 rowsums of E

// ---------------- helpers ----------------
__device__ __forceinline__ uint32_t smem_u32(const void* p) {
    uint32_t a;
    asm("{ .reg .u64 t; cvta.to.shared.u64 t, %1; cvt.u32.u64 %0, t; }" : "=r"(a) : "l"(p));
    return a;
}
__device__ __forceinline__ void cp16(uint32_t dst, const void* src) {
    asm volatile("cp.async.cg.shared.global [%0], [%1], 16;" :: "r"(dst), "l"(src) : "memory");
}
#define CP_COMMIT() asm volatile("cp.async.commit_group;" ::: "memory")
#define CP_WAIT1()  asm volatile("cp.async.wait_group 1;" ::: "memory")
#define CP_WAIT0()  asm volatile("cp.async.wait_group 0;" ::: "memory")

__device__ __forceinline__ void ldsm4(uint32_t* r, uint32_t addr) {
    asm volatile("ldmatrix.sync.aligned.m8n8.x4.shared.b16 {%0,%1,%2,%3}, [%4];"
        : "=r"(r[0]), "=r"(r[1]), "=r"(r[2]), "=r"(r[3]) : "r"(addr));
}
__device__ __forceinline__ void ldsm4t(uint32_t* r, uint32_t addr) {
    asm volatile("ldmatrix.sync.aligned.m8n8.x4.trans.shared.b16 {%0,%1,%2,%3}, [%4];"
        : "=r"(r[0]), "=r"(r[1]), "=r"(r[2]), "=r"(r[3]) : "r"(addr));
}
__device__ __forceinline__ void mma_bf16(float* c, const uint32_t* a, uint32_t b0, uint32_t b1) {
    asm volatile("mma.sync.aligned.m16n8k16.row.col.f32.bf16.bf16.f32 "
        "{%0,%1,%2,%3}, {%4,%5,%6,%7}, {%8,%9}, {%0,%1,%2,%3};"
        : "+f"(c[0]), "+f"(c[1]), "+f"(c[2]), "+f"(c[3])
        : "r"(a[0]), "r"(a[1]), "r"(a[2]), "r"(a[3]), "r"(b0), "r"(b1));
}

// split 8 f32 (two float4) into bf16 hi + lo (rounding residual) uint4s
__device__ __forceinline__ void split8(const float4& v0, const float4& v1,
                                       uint4& hi, uint4& lo) {
    float f[8] = {v0.x, v0.y, v0.z, v0.w, v1.x, v1.y, v1.z, v1.w};
    uint32_t h[4], l[4];
    #pragma unroll
    for (int i = 0; i < 4; i++) {
        __nv_bfloat16 h0 = __float2bfloat16(f[2 * i]);
        __nv_bfloat16 h1 = __float2bfloat16(f[2 * i + 1]);
        __nv_bfloat162 hp{h0, h1};
        __nv_bfloat162 lp{__float2bfloat16(f[2 * i]     - __bfloat162float(h0)),
                          __float2bfloat16(f[2 * i + 1] - __bfloat162float(h1))};
        h[i] = *(uint32_t*)&hp;
        l[i] = *(uint32_t*)&lp;
    }
    hi = make_uint4(h[0], h[1], h[2], h[3]);
    lo = make_uint4(l[0], l[1], l[2], l[3]);
}

// expm1 for u in [0, 1e-3]: u*(1 + u*(1/2 + u/6)), 3 FFMA, no MUFU
__device__ __forceinline__ float expm1_small(float u) {
    return u * fmaf(u, fmaf(u, 0.16666667f, 0.5f), 1.0f);
}
__device__ __forceinline__ uint32_t poly_pack2(float a, float b) {
    __nv_bfloat162 v = __floats2bfloat162_rn(expm1_small(a), expm1_small(b));
    return *(uint32_t*)&v;
}

// ============================================================
// GEMM1: E = exp(x @ W^T), bf16x3 inline split, mma.sync
// tile 32(M) x 32(N), K=1024, chunks of 64. 256 thr / 8 warps:
//   (wm,wn) pick the 16x16 quadrant, wk splits k-steps; smem-reduce at end.
// grid 128 = 16 ntiles x 8 mtiles
// ============================================================
constexpr int P1     = 72;                    // bf16 row pitch
constexpr int T1     = 32 * P1;               // one tile, bf16 elems
constexpr int STG1   = 4 * T1;                // Ahi|Alo|Bhi|Blo

__global__ __launch_bounds__(256) void gemm1_kernel(
    const float* __restrict__ x, const float* __restrict__ W)
{
    __shared__ __align__(16) __nv_bfloat16 sm[2 * STG1];
    __shared__ float sred[4][32][8];
    __shared__ float srs[2][32];

    const int tid = threadIdx.x, lane = tid & 31, wid = tid >> 5;
    const int nt = blockIdx.x & 15;
    const int m0 = (blockIdx.x >> 4) * 32, n0 = nt * 32;
    const uint32_t sb = smem_u32(sm);

    // loader mapping: 8 consecutive floats of A and of B per thread
    const int rowL = tid >> 3, off = (tid & 7) * 8;
    const float* aptr = x + (m0 + rowL) * 1024 + off;
    const float* bptr = W + (n0 + rowL) * 1024 + off;
    const uint32_t stsOff = (uint32_t)((rowL * P1 + off) * 2);

    float4 ra0, ra1, rb0, rb1;

    #define LDGC(c) do { \
        const float* _a = aptr + (c) * 64; \
        ra0 = *(const float4*)_a; ra1 = *(const float4*)(_a + 4); \
        const float* _b = bptr + (c) * 64; \
        rb0 = *(const float4*)_b; rb1 = *(const float4*)(_b + 4); \
    } while (0)

    #define STSC(s) do { \
        char* _base = (char*)sm + (s) * (STG1 * 2); \
        uint4 _hi, _lo; \
        split8(ra0, ra1, _hi, _lo); \
        *(uint4*)(_base + stsOff) = _hi; \
        *(uint4*)(_base + T1 * 2 + stsOff) = _lo; \
        split8(rb0, rb1, _hi, _lo); \
        *(uint4*)(_base + 2 * T1 * 2 + stsOff) = _hi; \
        *(uint4*)(_base + 3 * T1 * 2 + stsOff) = _lo; \
    } while (0)

    // compute mapping
    const int wn = wid & 1, wm = (wid >> 1) & 1, wk = wid >> 2;
    const int lrow = lane & 15;
    const int lk = (lane >> 4) << 3;
    const uint32_t aOff = (uint32_t)(((wm * 16 + lrow) * P1 + lk) * 2);
    const uint32_t bOff = (uint32_t)(((wn * 16 + lrow) * P1 + lk) * 2);

    float hh0[4] = {}, hh1[4] = {}, hl0[4] = {}, hl1[4] = {}, lh0[4] = {}, lh1[4] = {};

    LDGC(0);
    STSC(0);
    LDGC(1);
    __syncthreads();

    for (int c = 0; c < 16; c++) {
        if (c < 15) STSC((c + 1) & 1);
        if (c < 14) LDGC(c + 2);
        const uint32_t st = sb + (c & 1) * (STG1 * 2);
        #pragma unroll
        for (int j = 0; j < 2; j++) {
            const int ks = wk * 2 + j;
            uint32_t a_hi[4], a_lo[4], b_hi[4], b_lo[4];
            ldsm4(a_hi, st + aOff + ks * 32);
            ldsm4(a_lo, st + T1 * 2 + aOff + ks * 32);
            ldsm4(b_hi, st + 2 * T1 * 2 + bOff + ks * 32);
            ldsm4(b_lo, st + 3 * T1 * 2 + bOff + ks * 32);
            mma_bf16(hh0, a_hi, b_hi[0], b_hi[2]);
            mma_bf16(hh1, a_hi, b_hi[1], b_hi[3]);
            mma_bf16(hl0, a_hi, b_lo[0], b_lo[2]);
            mma_bf16(hl1, a_hi, b_lo[1], b_lo[3]);
            mma_bf16(lh0, a_lo, b_hi[0], b_hi[2]);
            mma_bf16(lh1, a_lo, b_hi[1], b_hi[3]);
        }
        __syncthreads();
    }
    #undef LDGC
    #undef STSC

    float acc0[4], acc1[4];
    #pragma unroll
    for (int i = 0; i < 4; i++) {
        acc0[i] = hh0[i] + hl0[i] + lh0[i];
        acc1[i] = hh1[i] + hl1[i] + lh1[i];
    }

    // k-split reduction: warp w (wk=0) += warp w+4 (wk=1)
    if (wk == 1) {
        #pragma unroll
        for (int i = 0; i < 4; i++) {
            sred[wid - 4][lane][i]     = acc0[i];
            sred[wid - 4][lane][4 + i] = acc1[i];
        }
    }
    __syncthreads();

    if (wk == 0) {
        #pragma unroll
        for (int i = 0; i < 4; i++) {
            acc0[i] += sred[wid][lane][i];
            acc1[i] += sred[wid][lane][4 + i];
        }
        // epilogue: exp, bf16 E, fp32 rowsum
        const int qr = lane >> 2;
        const int qc = (lane & 3) * 2;
        const int mrow0 = m0 + wm * 16 + qr;
        const int mrow1 = mrow0 + 8;
        float p0 = 0.f, p1 = 0.f;
        #pragma unroll
        for (int g = 0; g < 2; g++) {
            float* acc = g ? acc1 : acc0;
            float e0 = expf(acc[0]), e1 = expf(acc[1]);
            float e2 = expf(acc[2]), e3 = expf(acc[3]);
            p0 += e0 + e1; p1 += e2 + e3;
            const int n = n0 + wn * 16 + g * 8 + qc;
            __nv_bfloat162 v0 = __floats2bfloat162_rn(e0, e1);
            __nv_bfloat162 v1 = __floats2bfloat162_rn(e2, e3);
            *(uint32_t*)&g_Ebf[mrow0 * 512 + n] = *(uint32_t*)&v0;
            *(uint32_t*)&g_Ebf[mrow1 * 512 + n] = *(uint32_t*)&v1;
        }
        p0 += __shfl_xor_sync(0xFFFFFFFFu, p0, 1);
        p0 += __shfl_xor_sync(0xFFFFFFFFu, p0, 2);
        p1 += __shfl_xor_sync(0xFFFFFFFFu, p1, 1);
        p1 += __shfl_xor_sync(0xFFFFFFFFu, p1, 2);
        if ((lane & 3) == 0) {
            srs[wn][wm * 16 + qr]     = p0;
            srs[wn][wm * 16 + qr + 8] = p1;
        }
    }
    __syncthreads();
    if (tid < 32) g_rs[nt * 256 + m0 + tid] = srs[0][tid] + srs[1][tid];
}

// ============================================================
// GEMM2: y = E_bf16 @ expm1(u) + rowsum(E) + 512
// u loaded [k][n] as-is (poly inline), B via ldmatrix.trans.
// tile 32(M) x 64(N), K=512, chunks of 64. 256 thr / 8 warps (wk k-split).
// grid 128 = 16 ntiles x 8 mtiles
// ============================================================
constexpr int P2   = 72;
constexpr int ET2  = 32 * P2;                 // E tile elems
constexpr int UT2  = 64 * P2;                 // u tile elems
constexpr int STG2 = ET2 + UT2;

__global__ __launch_bounds__(256) void gemm2_kernel(
    const float* __restrict__ u, float* __restrict__ Y)
{
    __shared__ __align__(16) __nv_bfloat16 sm[2 * STG2];
    __shared__ float sred[4][32][16];
    __shared__ float rst[32];

    const int tid = threadIdx.x, lane = tid & 31, wid = tid >> 5;
    const int n0 = (blockIdx.x & 15) * 64;
    const int m0 = (blockIdx.x >> 4) * 32;
    const uint32_t sb = smem_u32(sm);

    if (tid < 32) {
        float s = 512.0f;
        #pragma unroll
        for (int j = 0; j < 16; j++) s += g_rs[j * 256 + m0 + tid];
        rst[tid] = s;
    }

    // E loader: cp.async, 32 rows x 8 segs
    const int rowE = tid >> 3, segE = tid & 7;
    const __nv_bfloat16* eptr = g_Ebf + (m0 + rowE) * 512 + segE * 8;
    const uint32_t eOffS = (uint32_t)((rowE * P2 + segE * 8) * 2);
    // u loader: 64 k-rows x 4 segs of 16 floats
    const int krow = tid >> 2, segU = (tid & 3) * 16;
    const float* uptr = u + krow * 1024 + n0 + segU;
    const uint32_t uOffS = (uint32_t)(ET2 * 2 + (krow * P2 + segU) * 2);

    float4 u0, u1, u2, u3;

    #define CPE(c) do { \
        cp16(sb + ((c) & 1) * (STG2 * 2) + eOffS, eptr + (c) * 64); \
        CP_COMMIT(); \
    } while (0)
    #define LDU(c) do { \
        const float* _p = uptr + (c) * 64 * 1024; \
        u0 = *(const float4*)_p;        u1 = *(const float4*)(_p + 4); \
        u2 = *(const float4*)(_p + 8);  u3 = *(const float4*)(_p + 12); \
    } while (0)
    #define STSU(s) do { \
        char* _b = (char*)sm + (s) * (STG2 * 2); \
        uint4 w0 = make_uint4(poly_pack2(u0.x, u0.y), poly_pack2(u0.z, u0.w), \
                              poly_pack2(u1.x, u1.y), poly_pack2(u1.z, u1.w)); \
        uint4 w1 = make_uint4(poly_pack2(u2.x, u2.y), poly_pack2(u2.z, u2.w), \
                              poly_pack2(u3.x, u3.y), poly_pack2(u3.z, u3.w)); \
        *(uint4*)(_b + uOffS) = w0; \
        *(uint4*)(_b + uOffS + 16) = w1; \
    } while (0)

    // compute mapping
    const int wn = wid & 1, wm = (wid >> 1) & 1, wk = wid >> 2;
    const int lrow = lane & 15;
    const int lk = (lane >> 4) << 3;
    const uint32_t aOff = (uint32_t)(((wm * 16 + lrow) * P2 + lk) * 2);
    // trans-B per-lane offset: rows = k (mat&1)*8+li, cols = n (mat>>1)*8
    const int li = lane & 7, kbit = (lane >> 3) & 1, nq = lane >> 4;
    const uint32_t tOff = (uint32_t)((((kbit * 8 + li) * P2) + nq * 8) * 2);

    float acc[4][4] = {};

    CPE(0);
    LDU(0);
    CPE(1);
    STSU(0);
    LDU(1);
    CP_WAIT1();
    __syncthreads();

    for (int c = 0; c < 8; c++) {
        if (c < 7) STSU((c + 1) & 1);
        if (c < 6) { CPE(c + 2); LDU(c + 2); }
        const uint32_t st = sb + (c & 1) * (STG2 * 2);
        const uint32_t stU = st + ET2 * 2;
        #pragma unroll
        for (int j = 0; j < 2; j++) {
            const int ks = wk * 2 + j;
            uint32_t a[4], bq0[4], bq1[4];
            ldsm4(a, st + aOff + ks * 32);
            ldsm4t(bq0, stU + tOff + ks * 16 * P2 * 2 + (wn * 32 + 0) * 2);
            ldsm4t(bq1, stU + tOff + ks * 16 * P2 * 2 + (wn * 32 + 16) * 2);
            mma_bf16(acc[0], a, bq0[0], bq0[1]);
            mma_bf16(acc[1], a, bq0[2], bq0[3]);
            mma_bf16(acc[2], a, bq1[0], bq1[1]);
            mma_bf16(acc[3], a, bq1[2], bq1[3]);
        }
        if (c >= 6) { CP_WAIT0(); } else { CP_WAIT1(); }
        __syncthreads();
    }
    #undef CPE
    #undef LDU
    #undef STSU

    // k-split reduction
    if (wk == 1) {
        #pragma unroll
        for (int g = 0; g < 4; g++)
            #pragma unroll
            for (int i = 0; i < 4; i++)
                sred[wid - 4][lane][g * 4 + i] = acc[g][i];
    }
    __syncthreads();

    if (wk == 0) {
        #pragma unroll
        for (int g = 0; g < 4; g++)
            #pragma unroll
            for (int i = 0; i < 4; i++)
                acc[g][i] += sred[wid][lane][g * 4 + i];

        const int qr = lane >> 2;
        const int qc = (lane & 3) * 2;
        const int mrow0 = m0 + wm * 16 + qr;
        const int mrow1 = mrow0 + 8;
        const float r0v = rst[wm * 16 + qr];
        const float r1v = rst[wm * 16 + qr + 8];
        #pragma unroll
        for (int g = 0; g < 4; g++) {
            const int n = n0 + wn * 32 + g * 8 + qc;
            *(float2*)(Y + mrow0 * 1024 + n) = make_float2(acc[g][0] + r0v, acc[g][1] + r0v);
            *(float2*)(Y + mrow1 * 1024 + n) = make_float2(acc[g][2] + r1v, acc[g][3] + r1v);
        }
    }
}

// ============================================================
extern "C" void kernel_launch(void* const* d_in, const int* in_sizes, int n_in,
                              void* d_out, int out_size)
{
    const float* x = (const float*)d_in[0];   // 256 x 1024
    const float* W = (const float*)d_in[1];   // 512 x 1024
    const float* u = (const float*)d_in[2];   // 512 x 1024
    float* y = (float*)d_out;                 // 256 x 1024

    gemm1_kernel<<<128, 256>>>(x, W);
    gemm2_kernel<<<128, 256>>>(u, y);
}